// round 1
// baseline (speedup 1.0000x reference)
#include <cuda_runtime.h>
#include <cstdint>
#include <cstddef>

// Problem dims
#define S_LEN 4096
#define HID   1024
#define EMB   1024
#define G4H   4096   // 4*HID
#define NBLK  128    // persistent recurrence blocks (1 per SM)
#define UPB   8      // hidden units per block (128*8 = 1024)

// ---------------- scratch (static device memory; no allocation) ----------------
__device__ float g_xgates[(size_t)S_LEN * G4H];        // 67 MB: precomputed x@W_ih^T + b
__device__ float g_hs[(size_t)(S_LEN + 1) * HID];      // h(0..S); row 0 = zeros
__device__ float g_v[HID];                              // W_tag^T @ w_hyb
__device__ float g_bc;                                  // b_tag.w_hyb + b_hyb
__device__ int   g_flags[NBLK];                         // per-block step counters

// ---------------- helpers ----------------
__device__ __forceinline__ int ld_acq(const int* p) {
    int v;
    asm volatile("ld.global.acquire.gpu.b32 %0, [%1];" : "=r"(v) : "l"(p) : "memory");
    return v;
}
__device__ __forceinline__ void st_rel(int* p, int v) {
    asm volatile("st.global.release.gpu.b32 [%0], %1;" :: "l"(p), "r"(v) : "memory");
}
__device__ __forceinline__ float sigm(float x) { return 1.f / (1.f + __expf(-x)); }
__device__ __forceinline__ float tanh_fast(float x) { return 2.f / (1.f + __expf(-2.f * x)) - 1.f; }

// ---------------- init: reset per-launch state + head bias constant ----------------
__global__ void init_kernel(const float* __restrict__ b_tag,
                            const float* __restrict__ w_hyb,
                            const float* __restrict__ b_hyb) {
    int tid = threadIdx.x;
    if (tid < HID) g_hs[tid] = 0.f;        // h(0) = 0
    if (tid < NBLK) g_flags[tid] = 0;      // step counters
    if (tid < 32) {
        float s = 0.f;
        for (int k = tid; k < HID; k += 32) s = fmaf(b_tag[k], w_hyb[k], s);
        #pragma unroll
        for (int o = 16; o; o >>= 1) s += __shfl_xor_sync(0xffffffffu, s, o);
        if (tid == 0) g_bc = s + b_hyb[0];
    }
}

// ---------------- head precompute: v[j] = sum_t w_hyb[t] * W_tag[t][j] ----------------
__global__ void vprec_kernel(const float* __restrict__ W_tag,
                             const float* __restrict__ w_hyb) {
    int j = threadIdx.x;  // 1024 threads
    float s = 0.f;
    #pragma unroll 8
    for (int t = 0; t < HID; t++)
        s = fmaf(__ldg(&w_hyb[t]), __ldg(&W_tag[(size_t)t * HID + j]), s);
    g_v[j] = s;
}

// ---------------- front GEMM: g_xgates[s][n] = emb[sentence[s]] . W_ih[n] + b_ih[n]+b_hh[n] ----------------
#define BM 64
#define BN 64
#define BK 16

__global__ void __launch_bounds__(256) gemm_xgates(
    const int*   __restrict__ sentence,
    const float* __restrict__ emb,
    const float* __restrict__ W_ih,
    const float* __restrict__ b_ih,
    const float* __restrict__ b_hh) {
    __shared__ __align__(16) float As[BK][BM + 4];
    __shared__ __align__(16) float Bs[BK][BN + 4];
    int tid = threadIdx.x;
    int bm = blockIdx.y, bn = blockIdx.x;
    int tx = tid & 15, ty = tid >> 4;     // 16x16 thread grid, 4x4 micro-tile each
    int lrow = tid >> 2;                  // 0..63 (tile row for loads)
    int lk   = (tid & 3) << 2;            // 0,4,8,12 (k offset, float4)

    const float* aptr = emb + (size_t)__ldg(&sentence[bm * BM + lrow]) * EMB + lk;
    const float* bptr = W_ih + (size_t)(bn * BN + lrow) * EMB + lk;

    float acc[4][4] = {};
    for (int kt = 0; kt < EMB; kt += BK) {
        float4 av = *(const float4*)(aptr + kt);
        float4 bv = *(const float4*)(bptr + kt);
        As[lk + 0][lrow] = av.x; As[lk + 1][lrow] = av.y;
        As[lk + 2][lrow] = av.z; As[lk + 3][lrow] = av.w;
        Bs[lk + 0][lrow] = bv.x; Bs[lk + 1][lrow] = bv.y;
        Bs[lk + 2][lrow] = bv.z; Bs[lk + 3][lrow] = bv.w;
        __syncthreads();
        #pragma unroll
        for (int kk = 0; kk < BK; kk++) {
            float4 a = *(const float4*)&As[kk][ty << 2];
            float4 b = *(const float4*)&Bs[kk][tx << 2];
            acc[0][0] = fmaf(a.x, b.x, acc[0][0]);
            acc[0][1] = fmaf(a.x, b.y, acc[0][1]);
            acc[0][2] = fmaf(a.x, b.z, acc[0][2]);
            acc[0][3] = fmaf(a.x, b.w, acc[0][3]);
            acc[1][0] = fmaf(a.y, b.x, acc[1][0]);
            acc[1][1] = fmaf(a.y, b.y, acc[1][1]);
            acc[1][2] = fmaf(a.y, b.z, acc[1][2]);
            acc[1][3] = fmaf(a.y, b.w, acc[1][3]);
            acc[2][0] = fmaf(a.z, b.x, acc[2][0]);
            acc[2][1] = fmaf(a.z, b.y, acc[2][1]);
            acc[2][2] = fmaf(a.z, b.z, acc[2][2]);
            acc[2][3] = fmaf(a.z, b.w, acc[2][3]);
            acc[3][0] = fmaf(a.w, b.x, acc[3][0]);
            acc[3][1] = fmaf(a.w, b.y, acc[3][1]);
            acc[3][2] = fmaf(a.w, b.z, acc[3][2]);
            acc[3][3] = fmaf(a.w, b.w, acc[3][3]);
        }
        __syncthreads();
    }
    int n0 = bn * BN + (tx << 2);
    float4 bias;
    bias.x = b_ih[n0 + 0] + b_hh[n0 + 0];
    bias.y = b_ih[n0 + 1] + b_hh[n0 + 1];
    bias.z = b_ih[n0 + 2] + b_hh[n0 + 2];
    bias.w = b_ih[n0 + 3] + b_hh[n0 + 3];
    #pragma unroll
    for (int i = 0; i < 4; i++) {
        int m = bm * BM + (ty << 2) + i;
        float4 o;
        o.x = acc[i][0] + bias.x;
        o.y = acc[i][1] + bias.y;
        o.z = acc[i][2] + bias.z;
        o.w = acc[i][3] + bias.w;
        *(float4*)&g_xgates[(size_t)m * G4H + n0] = o;
    }
}

// ---------------- persistent LSTM recurrence ----------------
// 128 blocks x 1024 threads. Block b owns hidden units [8b, 8b+8).
// Warp w: group = w>>2 (local unit), chunk = w&3 (256-wide slice of h).
// Warp computes 4 gate-row partial dots (i,f,g,o of its unit) over its chunk.
// Weights register-resident: 32 floats/thread.
__global__ void __launch_bounds__(1024, 1) lstm_rec(const float* __restrict__ W_hh) {
    __shared__ float sh_h[HID];
    __shared__ float part[32][4];
    __shared__ float gp[8][4];
    __shared__ float c_s[8];

    int tid  = threadIdx.x;
    int lane = tid & 31, warp = tid >> 5;
    int group = warp >> 2, chunk = warp & 3;
    int b = blockIdx.x;
    int unit = b * UPB + group;

    // Load register-resident weights: w[j][k] = W_hh[j*H + unit][chunk*256 + lane + 32k]
    float w[4][8];
    #pragma unroll
    for (int j = 0; j < 4; j++) {
        const float* wr = W_hh + (size_t)(j * HID + unit) * HID + chunk * 256 + lane;
        #pragma unroll
        for (int k = 0; k < 8; k++) w[j][k] = wr[k * 32];
    }
    if (tid < 8) c_s[tid] = 0.f;
    __syncthreads();

    const int hb = chunk * 256 + lane;
    for (int t = 1; t <= S_LEN; t++) {
        // Wait: all blocks finished step t-1 (flags start at 0 = h(0) ready)
        if (tid < NBLK) {
            while (ld_acq(&g_flags[tid]) < t - 1) { }
        }
        __syncthreads();  // A

        // Stage h(t-1) into smem; prefetch this block's x_gates slice
        sh_h[tid] = g_hs[(size_t)(t - 1) * HID + tid];
        float xg = 0.f;
        if (tid < 32)
            xg = __ldg(&g_xgates[(size_t)(t - 1) * G4H + (tid & 3) * HID + b * UPB + (tid >> 2)]);
        __syncthreads();  // B

        // Partial dots: 4 gate rows x 256 elements per warp
        float a0 = 0.f, a1 = 0.f, a2 = 0.f, a3 = 0.f;
        #pragma unroll
        for (int k = 0; k < 8; k++) {
            float hv = sh_h[hb + k * 32];
            a0 = fmaf(w[0][k], hv, a0);
            a1 = fmaf(w[1][k], hv, a1);
            a2 = fmaf(w[2][k], hv, a2);
            a3 = fmaf(w[3][k], hv, a3);
        }
        #pragma unroll
        for (int o = 16; o; o >>= 1) {
            a0 += __shfl_xor_sync(0xffffffffu, a0, o);
            a1 += __shfl_xor_sync(0xffffffffu, a1, o);
            a2 += __shfl_xor_sync(0xffffffffu, a2, o);
            a3 += __shfl_xor_sync(0xffffffffu, a3, o);
        }
        if (lane == 0) {
            part[warp][0] = a0; part[warp][1] = a1;
            part[warp][2] = a2; part[warp][3] = a3;
        }
        __syncthreads();  // C

        // Combine chunks + gate math + write h (warp 0 only)
        if (tid < 32) {
            int g = tid >> 2, j = tid & 3;
            float s = part[(g << 2) + 0][j] + part[(g << 2) + 1][j] +
                      part[(g << 2) + 2][j] + part[(g << 2) + 3][j] + xg;
            gp[g][j] = s;
        }
        __syncwarp();
        if (tid < 8) {
            float c  = c_s[tid];
            float iv = sigm(gp[tid][0]);
            float fv = sigm(gp[tid][1]);
            float gv = tanh_fast(gp[tid][2]);
            float ov = sigm(gp[tid][3]);
            c = fmaf(fv, c, iv * gv);
            c_s[tid] = c;
            float h = ov * tanh_fast(c);
            g_hs[(size_t)t * HID + b * UPB + tid] = h;
            __threadfence();
        }
        __syncwarp();
        if (tid == 0) st_rel(&g_flags[b], t);
    }
}

// ---------------- head: out[s] = sigmoid(hs(s+1) . v + bc) ----------------
__global__ void head_kernel(float* __restrict__ out) {
    int s = blockIdx.x;
    int tid = threadIdx.x;  // 128
    const float* hrow = g_hs + (size_t)(s + 1) * HID;
    float p = 0.f;
    #pragma unroll
    for (int k = 0; k < 8; k++)
        p = fmaf(hrow[tid + 128 * k], g_v[tid + 128 * k], p);
    #pragma unroll
    for (int o = 16; o; o >>= 1) p += __shfl_xor_sync(0xffffffffu, p, o);
    __shared__ float red[4];
    if ((tid & 31) == 0) red[tid >> 5] = p;
    __syncthreads();
    if (tid == 0) {
        float tot = red[0] + red[1] + red[2] + red[3] + g_bc;
        out[s] = sigm(tot);
    }
}

// ---------------- launch ----------------
extern "C" void kernel_launch(void* const* d_in, const int* in_sizes, int n_in,
                              void* d_out, int out_size) {
    const int*   sentence = (const int*)  d_in[0];
    const float* emb      = (const float*)d_in[1];
    const float* W_ih     = (const float*)d_in[2];
    const float* W_hh     = (const float*)d_in[3];
    const float* b_ih     = (const float*)d_in[4];
    const float* b_hh     = (const float*)d_in[5];
    const float* W_tag    = (const float*)d_in[6];
    const float* b_tag    = (const float*)d_in[7];
    const float* W_hyb    = (const float*)d_in[8];
    const float* b_hyb    = (const float*)d_in[9];
    float* out = (float*)d_out;

    init_kernel<<<1, 1024>>>(b_tag, W_hyb, b_hyb);
    vprec_kernel<<<1, 1024>>>(W_tag, W_hyb);
    dim3 g(G4H / BN, S_LEN / BM);
    gemm_xgates<<<g, 256>>>(sentence, emb, W_ih, b_ih, b_hh);
    lstm_rec<<<NBLK, 1024>>>(W_hh);
    head_kernel<<<S_LEN, 128>>>(out);
}

// round 5
// speedup vs baseline: 2.5203x; 2.5203x over previous
#include <cuda_runtime.h>
#include <cstdint>
#include <cstddef>

// Problem dims
#define S_LEN 4096
#define HID   1024
#define EMB   1024
#define G4H   4096   // 4*HID
#define NBLK  128    // persistent recurrence blocks (1 per SM)
#define UPB   8      // hidden units per block (128*8 = 1024)

// ---------------- scratch (static device memory; no allocation) ----------------
__device__ __align__(16) float g_xgates[(size_t)S_LEN * G4H];   // 67 MB
__device__ __align__(16) float g_hs[(size_t)(S_LEN + 1) * HID]; // h(0..S); row 0 zeros
__device__ int   g_cnt;                                          // global step-completion counter
__device__ float g_v[HID];                                       // W_tag^T @ w_hyb
__device__ float g_bc;                                           // b_tag.w_hyb + b_hyb

// ---------------- helpers (STRONG ops only for sync) ----------------
__device__ __forceinline__ int ld_acq(const int* p) {
    int v;
    asm volatile("ld.global.acquire.gpu.b32 %0, [%1];" : "=r"(v) : "l"(p) : "memory");
    return v;
}
__device__ __forceinline__ float sigm(float x) { return 1.f / (1.f + __expf(-x)); }
__device__ __forceinline__ float tanh_fast(float x) { return 2.f / (1.f + __expf(-2.f * x)) - 1.f; }

// ---------------- init: h0 = 0, counter = 0, head bias constant ----------------
__global__ void init_kernel(const float* __restrict__ b_tag,
                            const float* __restrict__ w_hyb,
                            const float* __restrict__ b_hyb) {
    int tid = threadIdx.x;               // 1024 threads
    if (tid < HID) g_hs[tid] = 0.f;      // h(0) = 0
    if (tid == 0) g_cnt = 0;             // step counter
    if (tid < 32) {
        float s = 0.f;
        for (int k = tid; k < HID; k += 32) s = fmaf(b_tag[k], w_hyb[k], s);
        #pragma unroll
        for (int o = 16; o; o >>= 1) s += __shfl_xor_sync(0xffffffffu, s, o);
        if (tid == 0) g_bc = s + b_hyb[0];
    }
}

// ---------------- head precompute: v[j] = sum_t w_hyb[t] * W_tag[t][j] ----------------
__global__ void vprec_kernel(const float* __restrict__ W_tag,
                             const float* __restrict__ w_hyb) {
    int j = threadIdx.x;  // 1024 threads
    float s = 0.f;
    #pragma unroll 8
    for (int t = 0; t < HID; t++)
        s = fmaf(__ldg(&w_hyb[t]), __ldg(&W_tag[(size_t)t * HID + j]), s);
    g_v[j] = s;
}

// ---------------- front GEMM: g_xgates[s][n] = emb[sentence[s]] . W_ih[n] + bias ----------------
#define BM 64
#define BN 64
#define BK 16

__global__ void __launch_bounds__(256) gemm_xgates(
    const int*   __restrict__ sentence,
    const float* __restrict__ emb,
    const float* __restrict__ W_ih,
    const float* __restrict__ b_ih,
    const float* __restrict__ b_hh) {
    __shared__ __align__(16) float As[BK][BM + 4];
    __shared__ __align__(16) float Bs[BK][BN + 4];
    int tid = threadIdx.x;
    int bm = blockIdx.y, bn = blockIdx.x;
    int tx = tid & 15, ty = tid >> 4;     // 16x16 thread grid, 4x4 micro-tile each
    int lrow = tid >> 2;                  // 0..63 (tile row for loads)
    int lk   = (tid & 3) << 2;            // 0,4,8,12 (k offset, float4)

    const float* aptr = emb + (size_t)__ldg(&sentence[bm * BM + lrow]) * EMB + lk;
    const float* bptr = W_ih + (size_t)(bn * BN + lrow) * EMB + lk;

    float acc[4][4] = {};
    for (int kt = 0; kt < EMB; kt += BK) {
        float4 av = *(const float4*)(aptr + kt);
        float4 bv = *(const float4*)(bptr + kt);
        As[lk + 0][lrow] = av.x; As[lk + 1][lrow] = av.y;
        As[lk + 2][lrow] = av.z; As[lk + 3][lrow] = av.w;
        Bs[lk + 0][lrow] = bv.x; Bs[lk + 1][lrow] = bv.y;
        Bs[lk + 2][lrow] = bv.z; Bs[lk + 3][lrow] = bv.w;
        __syncthreads();
        #pragma unroll
        for (int kk = 0; kk < BK; kk++) {
            float4 a = *(const float4*)&As[kk][ty << 2];
            float4 b = *(const float4*)&Bs[kk][tx << 2];
            acc[0][0] = fmaf(a.x, b.x, acc[0][0]);
            acc[0][1] = fmaf(a.x, b.y, acc[0][1]);
            acc[0][2] = fmaf(a.x, b.z, acc[0][2]);
            acc[0][3] = fmaf(a.x, b.w, acc[0][3]);
            acc[1][0] = fmaf(a.y, b.x, acc[1][0]);
            acc[1][1] = fmaf(a.y, b.y, acc[1][1]);
            acc[1][2] = fmaf(a.y, b.z, acc[1][2]);
            acc[1][3] = fmaf(a.y, b.w, acc[1][3]);
            acc[2][0] = fmaf(a.z, b.x, acc[2][0]);
            acc[2][1] = fmaf(a.z, b.y, acc[2][1]);
            acc[2][2] = fmaf(a.z, b.z, acc[2][2]);
            acc[2][3] = fmaf(a.z, b.w, acc[2][3]);
            acc[3][0] = fmaf(a.w, b.x, acc[3][0]);
            acc[3][1] = fmaf(a.w, b.y, acc[3][1]);
            acc[3][2] = fmaf(a.w, b.z, acc[3][2]);
            acc[3][3] = fmaf(a.w, b.w, acc[3][3]);
        }
        __syncthreads();
    }
    int n0 = bn * BN + (tx << 2);
    float4 bias;
    bias.x = b_ih[n0 + 0] + b_hh[n0 + 0];
    bias.y = b_ih[n0 + 1] + b_hh[n0 + 1];
    bias.z = b_ih[n0 + 2] + b_hh[n0 + 2];
    bias.w = b_ih[n0 + 3] + b_hh[n0 + 3];
    #pragma unroll
    for (int i = 0; i < 4; i++) {
        int m = bm * BM + (ty << 2) + i;
        float4 o;
        o.x = acc[i][0] + bias.x;
        o.y = acc[i][1] + bias.y;
        o.z = acc[i][2] + bias.z;
        o.w = acc[i][3] + bias.w;
        *(float4*)&g_xgates[(size_t)m * G4H + n0] = o;
    }
}

// ---------------- persistent LSTM recurrence (single-counter, strong sync) ----------------
// 128 blocks x 1024 threads. Block b owns hidden units [8b, 8b+8).
// Publish: tid<8 store h -> __threadfence -> __syncwarp -> tid0 atomicAdd(g_cnt,1).
// Wait: tid0 spins ld.acquire.gpu(g_cnt) >= 128*(t-1); __syncthreads propagates.
__global__ void __launch_bounds__(1024, 1) lstm_rec(const float* __restrict__ W_hh) {
    __shared__ __align__(16) float sh_h[HID];
    __shared__ float part[32][4];
    __shared__ float gp[8][4];
    __shared__ float c_s[8];

    int tid  = threadIdx.x;
    int lane = tid & 31, warp = tid >> 5;
    int group = warp >> 2, chunk = warp & 3;
    int b = blockIdx.x;
    int unit = b * UPB + group;

    // Register-resident weights: w[j][k] = W_hh[j*H + unit][chunk*256 + lane + 32k]
    float w[4][8];
    #pragma unroll
    for (int j = 0; j < 4; j++) {
        const float* wr = W_hh + (size_t)(j * HID + unit) * HID + chunk * 256 + lane;
        #pragma unroll
        for (int k = 0; k < 8; k++) w[j][k] = wr[k * 32];
    }
    if (tid < 8) c_s[tid] = 0.f;
    __syncthreads();

    const int hb = chunk * 256 + lane;
    int tgt = 0;  // = NBLK * (t-1)
    for (int t = 1; t <= S_LEN; t++, tgt += NBLK) {
        // xg prefetch FIRST (register; DRAM latency hides under the wait)
        float xg = 0.f;
        if (tid < 32)
            xg = __ldg(&g_xgates[(size_t)(t - 1) * G4H + (tid & 3) * HID + b * UPB + (tid >> 2)]);

        // Leader acquire-wait on the global counter
        if (tid == 0) {
            while (ld_acq(&g_cnt) < tgt) { }
        }
        __syncthreads();  // A: propagate acquire block-wide

        // Stage h(t-1) into smem (float4, tid<256; plain loads post-acquire)
        if (tid < 256) {
            float4 v = *((const float4*)(g_hs + (size_t)(t - 1) * HID) + tid);
            *(float4*)&sh_h[tid << 2] = v;
        }
        __syncthreads();  // B

        // Partial dots: 4 gate rows x 256 elements per warp
        float a0 = 0.f, a1 = 0.f, a2 = 0.f, a3 = 0.f;
        #pragma unroll
        for (int k = 0; k < 8; k++) {
            float hv = sh_h[hb + k * 32];
            a0 = fmaf(w[0][k], hv, a0);
            a1 = fmaf(w[1][k], hv, a1);
            a2 = fmaf(w[2][k], hv, a2);
            a3 = fmaf(w[3][k], hv, a3);
        }
        #pragma unroll
        for (int o = 16; o; o >>= 1) {
            a0 += __shfl_xor_sync(0xffffffffu, a0, o);
            a1 += __shfl_xor_sync(0xffffffffu, a1, o);
            a2 += __shfl_xor_sync(0xffffffffu, a2, o);
            a3 += __shfl_xor_sync(0xffffffffu, a3, o);
        }
        if (lane == 0) {
            part[warp][0] = a0; part[warp][1] = a1;
            part[warp][2] = a2; part[warp][3] = a3;
        }
        __syncthreads();  // C

        // Combine chunks (register xg), gate math, publish h + counter
        if (tid < 32) {
            int g = tid >> 2, j = tid & 3;
            float s = part[(g << 2) + 0][j] + part[(g << 2) + 1][j] +
                      part[(g << 2) + 2][j] + part[(g << 2) + 3][j] + xg;
            gp[g][j] = s;
        }
        __syncwarp();
        if (tid < 8) {
            float iv = sigm(gp[tid][0]);
            float fv = sigm(gp[tid][1]);
            float gv = tanh_fast(gp[tid][2]);
            float ov = sigm(gp[tid][3]);
            float c  = fmaf(fv, c_s[tid], iv * gv);
            c_s[tid] = c;
            g_hs[(size_t)t * HID + b * UPB + tid] = ov * tanh_fast(c);
            __threadfence();            // release: h stores ordered before counter bump
        }
        __syncwarp();
        if (tid == 0) atomicAdd(&g_cnt, 1);   // strong publish
    }
}

// ---------------- head: out[s] = sigmoid(hs(s+1) . v + bc) ----------------
__global__ void head_kernel(float* __restrict__ out) {
    int s = blockIdx.x;
    int tid = threadIdx.x;  // 128
    const float* hrow = g_hs + (size_t)(s + 1) * HID;
    float p = 0.f;
    #pragma unroll
    for (int k = 0; k < 8; k++)
        p = fmaf(hrow[tid + 128 * k], g_v[tid + 128 * k], p);
    #pragma unroll
    for (int o = 16; o; o >>= 1) p += __shfl_xor_sync(0xffffffffu, p, o);
    __shared__ float red[4];
    if ((tid & 31) == 0) red[tid >> 5] = p;
    __syncthreads();
    if (tid == 0) {
        float tot = red[0] + red[1] + red[2] + red[3] + g_bc;
        out[s] = sigm(tot);
    }
}

// ---------------- launch ----------------
extern "C" void kernel_launch(void* const* d_in, const int* in_sizes, int n_in,
                              void* d_out, int out_size) {
    const int*   sentence = (const int*)  d_in[0];
    const float* emb      = (const float*)d_in[1];
    const float* W_ih     = (const float*)d_in[2];
    const float* W_hh     = (const float*)d_in[3];
    const float* b_ih     = (const float*)d_in[4];
    const float* b_hh     = (const float*)d_in[5];
    const float* W_tag    = (const float*)d_in[6];
    const float* b_tag    = (const float*)d_in[7];
    const float* W_hyb    = (const float*)d_in[8];
    const float* b_hyb    = (const float*)d_in[9];
    float* out = (float*)d_out;

    init_kernel<<<1, 1024>>>(b_tag, W_hyb, b_hyb);
    vprec_kernel<<<1, 1024>>>(W_tag, W_hyb);
    dim3 g(G4H / BN, S_LEN / BM);
    gemm_xgates<<<g, 256>>>(sentence, emb, W_ih, b_ih, b_hh);
    lstm_rec<<<NBLK, 1024>>>(W_hh);
    head_kernel<<<S_LEN, 128>>>(out);
}

// round 6
// speedup vs baseline: 3.0688x; 1.2176x over previous
#include <cuda_runtime.h>
#include <cstdint>
#include <cstddef>

// Problem dims
#define S_LEN 4096
#define HID   1024
#define EMB   1024
#define G4H   4096   // 4*HID
#define NBLK  128    // persistent recurrence blocks (1 per SM)
#define UPB   8      // hidden units per block (128*8 = 1024)

// ---------------- scratch (static device memory; no allocation) ----------------
__device__ __align__(16) float g_xgates[(size_t)S_LEN * G4H];   // 67 MB
__device__ __align__(16) float g_hs[(size_t)(S_LEN + 1) * HID]; // h(0..S); row 0 zeros
__device__ int   g_cnt;                                          // global step-completion counter
__device__ float g_v[HID];                                       // W_tag^T @ w_hyb
__device__ float g_bc;                                           // b_tag.w_hyb + b_hyb

// ---------------- helpers (STRONG ops only for sync) ----------------
__device__ __forceinline__ int ld_acq(const int* p) {
    int v;
    asm volatile("ld.global.acquire.gpu.b32 %0, [%1];" : "=r"(v) : "l"(p) : "memory");
    return v;
}
__device__ __forceinline__ void red_add_release(int* p, int v) {
    asm volatile("red.release.gpu.global.add.s32 [%0], %1;" :: "l"(p), "r"(v) : "memory");
}
__device__ __forceinline__ void fma2(unsigned long long& d, unsigned long long a, unsigned long long b) {
    asm("fma.rn.f32x2 %0, %1, %2, %0;" : "+l"(d) : "l"(a), "l"(b));
}
__device__ __forceinline__ float2 unpack2(unsigned long long v) {
    float2 f;
    asm("mov.b64 {%0,%1}, %2;" : "=f"(f.x), "=f"(f.y) : "l"(v));
    return f;
}
__device__ __forceinline__ float sigm(float x) { return 1.f / (1.f + __expf(-x)); }
__device__ __forceinline__ float tanh_fast(float x) { return 2.f / (1.f + __expf(-2.f * x)) - 1.f; }

// ---------------- init: h0 = 0, counter = 0, head bias constant ----------------
__global__ void init_kernel(const float* __restrict__ b_tag,
                            const float* __restrict__ w_hyb,
                            const float* __restrict__ b_hyb) {
    int tid = threadIdx.x;               // 1024 threads
    if (tid < HID) g_hs[tid] = 0.f;      // h(0) = 0
    if (tid == 0) g_cnt = 0;             // step counter
    if (tid < 32) {
        float s = 0.f;
        for (int k = tid; k < HID; k += 32) s = fmaf(b_tag[k], w_hyb[k], s);
        #pragma unroll
        for (int o = 16; o; o >>= 1) s += __shfl_xor_sync(0xffffffffu, s, o);
        if (tid == 0) g_bc = s + b_hyb[0];
    }
}

// ---------------- head precompute: v[j] = sum_t w_hyb[t] * W_tag[t][j] ----------------
__global__ void vprec_kernel(const float* __restrict__ W_tag,
                             const float* __restrict__ w_hyb) {
    int j = threadIdx.x;  // 1024 threads
    float s = 0.f;
    #pragma unroll 8
    for (int t = 0; t < HID; t++)
        s = fmaf(__ldg(&w_hyb[t]), __ldg(&W_tag[(size_t)t * HID + j]), s);
    g_v[j] = s;
}

// ---------------- front GEMM: g_xgates[s][n] = emb[sentence[s]] . W_ih[n] + bias ----------------
#define BM 64
#define BN 64
#define BK 16

__global__ void __launch_bounds__(256) gemm_xgates(
    const int*   __restrict__ sentence,
    const float* __restrict__ emb,
    const float* __restrict__ W_ih,
    const float* __restrict__ b_ih,
    const float* __restrict__ b_hh) {
    __shared__ __align__(16) float As[BK][BM + 4];
    __shared__ __align__(16) float Bs[BK][BN + 4];
    int tid = threadIdx.x;
    int bm = blockIdx.y, bn = blockIdx.x;
    int tx = tid & 15, ty = tid >> 4;     // 16x16 thread grid, 4x4 micro-tile each
    int lrow = tid >> 2;                  // 0..63 (tile row for loads)
    int lk   = (tid & 3) << 2;            // 0,4,8,12 (k offset, float4)

    const float* aptr = emb + (size_t)__ldg(&sentence[bm * BM + lrow]) * EMB + lk;
    const float* bptr = W_ih + (size_t)(bn * BN + lrow) * EMB + lk;

    float acc[4][4] = {};
    for (int kt = 0; kt < EMB; kt += BK) {
        float4 av = *(const float4*)(aptr + kt);
        float4 bv = *(const float4*)(bptr + kt);
        As[lk + 0][lrow] = av.x; As[lk + 1][lrow] = av.y;
        As[lk + 2][lrow] = av.z; As[lk + 3][lrow] = av.w;
        Bs[lk + 0][lrow] = bv.x; Bs[lk + 1][lrow] = bv.y;
        Bs[lk + 2][lrow] = bv.z; Bs[lk + 3][lrow] = bv.w;
        __syncthreads();
        #pragma unroll
        for (int kk = 0; kk < BK; kk++) {
            float4 a = *(const float4*)&As[kk][ty << 2];
            float4 b = *(const float4*)&Bs[kk][tx << 2];
            acc[0][0] = fmaf(a.x, b.x, acc[0][0]);
            acc[0][1] = fmaf(a.x, b.y, acc[0][1]);
            acc[0][2] = fmaf(a.x, b.z, acc[0][2]);
            acc[0][3] = fmaf(a.x, b.w, acc[0][3]);
            acc[1][0] = fmaf(a.y, b.x, acc[1][0]);
            acc[1][1] = fmaf(a.y, b.y, acc[1][1]);
            acc[1][2] = fmaf(a.y, b.z, acc[1][2]);
            acc[1][3] = fmaf(a.y, b.w, acc[1][3]);
            acc[2][0] = fmaf(a.z, b.x, acc[2][0]);
            acc[2][1] = fmaf(a.z, b.y, acc[2][1]);
            acc[2][2] = fmaf(a.z, b.z, acc[2][2]);
            acc[2][3] = fmaf(a.z, b.w, acc[2][3]);
            acc[3][0] = fmaf(a.w, b.x, acc[3][0]);
            acc[3][1] = fmaf(a.w, b.y, acc[3][1]);
            acc[3][2] = fmaf(a.w, b.z, acc[3][2]);
            acc[3][3] = fmaf(a.w, b.w, acc[3][3]);
        }
        __syncthreads();
    }
    int n0 = bn * BN + (tx << 2);
    float4 bias;
    bias.x = b_ih[n0 + 0] + b_hh[n0 + 0];
    bias.y = b_ih[n0 + 1] + b_hh[n0 + 1];
    bias.z = b_ih[n0 + 2] + b_hh[n0 + 2];
    bias.w = b_ih[n0 + 3] + b_hh[n0 + 3];
    #pragma unroll
    for (int i = 0; i < 4; i++) {
        int m = bm * BM + (ty << 2) + i;
        float4 o;
        o.x = acc[i][0] + bias.x;
        o.y = acc[i][1] + bias.y;
        o.z = acc[i][2] + bias.z;
        o.w = acc[i][3] + bias.w;
        *(float4*)&g_xgates[(size_t)m * G4H + n0] = o;
    }
}

// ---------------- persistent LSTM recurrence (lean step, strong sync) ----------------
// 128 blocks x 1024 threads. Block b owns hidden units [8b, 8b+8).
// Warp w: unit group g=w>>2, chunk c=w&3 (256-wide h slice as 128 f32 pairs).
// Dots use fma.rn.f32x2 on register-resident packed weights.
// Reduce: 3 xor-shuffle levels -> lanes 0..3 hold mod-4 partials -> smem ->
// warp 0 finishes (combine + activations + c update + h store + release-publish).
// Warp 1 lane 0 is the poller for the NEXT step (overlaps warp 0's tail).
__global__ void __launch_bounds__(1024, 1) lstm_rec(const float* __restrict__ W_hh) {
    // part_s[g][j][c][q]: unit-group g, gate j, chunk c, lane-group q
    __shared__ float part_s[8][4][4][4];

    int tid  = threadIdx.x;
    int lane = tid & 31, warp = tid >> 5;
    int group = warp >> 2, chunk = warp & 3;
    int b = blockIdx.x;
    int unit = b * UPB + group;

    // Packed register weights: w2[j][k] covers elements (c*256 + 2*lane + 64k, +1)
    unsigned long long w2[4][4];
    #pragma unroll
    for (int j = 0; j < 4; j++) {
        const float* wr = W_hh + (size_t)(j * HID + unit) * HID + (chunk << 8) + (lane << 1);
        #pragma unroll
        for (int k = 0; k < 4; k++)
            w2[j][k] = *(const unsigned long long*)(wr + 64 * k);
    }

    // Warp 0 per-lane persistent state: c for unit (lane>>2) lives in lanes with (lane&3)==0
    float c_reg = 0.f;
    // Warp 0: xg for this lane's gate row (gate j=lane&3, unit u=lane>>2), prefetched
    float xg_cur = 0.f;
    if (warp == 0)
        xg_cur = __ldg(&g_xgates[(size_t)0 * G4H + (lane & 3) * HID + b * UPB + (lane >> 2)]);

    __syncthreads();

    int tgt = 0;  // = NBLK * (t-1)
    for (int t = 1; t <= S_LEN; t++, tgt += NBLK) {
        // Poller: warp 1 lane 0 acquire-spins on the global counter
        if (tid == 32) {
            while (ld_acq(&g_cnt) < tgt) { }
        }
        __syncthreads();  // A: h(t-1) globally visible to the whole block

        // Warp 0: prefetch next step's xg (latency hidden under this step)
        float xg_nxt = 0.f;
        if (warp == 0) {
            int tp = (t < S_LEN) ? t : 0;
            xg_nxt = __ldg(&g_xgates[(size_t)tp * G4H + (lane & 3) * HID + b * UPB + (lane >> 2)]);
        }

        // Direct global loads of this thread's 4 h pairs (L2 hit, no smem staging)
        const float* hrow = g_hs + (size_t)(t - 1) * HID + (chunk << 8) + (lane << 1);
        unsigned long long h0 = *(const unsigned long long*)(hrow);
        unsigned long long h1 = *(const unsigned long long*)(hrow + 64);
        unsigned long long h2 = *(const unsigned long long*)(hrow + 128);
        unsigned long long h3 = *(const unsigned long long*)(hrow + 192);

        // Packed dots: 4 gate rows x 4 pairs
        unsigned long long a2_0 = 0ull, a2_1 = 0ull, a2_2 = 0ull, a2_3 = 0ull;
        fma2(a2_0, w2[0][0], h0); fma2(a2_1, w2[1][0], h0);
        fma2(a2_2, w2[2][0], h0); fma2(a2_3, w2[3][0], h0);
        fma2(a2_0, w2[0][1], h1); fma2(a2_1, w2[1][1], h1);
        fma2(a2_2, w2[2][1], h1); fma2(a2_3, w2[3][1], h1);
        fma2(a2_0, w2[0][2], h2); fma2(a2_1, w2[1][2], h2);
        fma2(a2_2, w2[2][2], h2); fma2(a2_3, w2[3][2], h2);
        fma2(a2_0, w2[0][3], h3); fma2(a2_1, w2[1][3], h3);
        fma2(a2_2, w2[2][3], h3); fma2(a2_3, w2[3][3], h3);

        float2 f0 = unpack2(a2_0), f1 = unpack2(a2_1), f2 = unpack2(a2_2), f3 = unpack2(a2_3);
        float s0 = f0.x + f0.y, s1 = f1.x + f1.y, s2 = f2.x + f2.y, s3 = f3.x + f3.y;

        // 3 xor-shuffle levels: lane q (q=lane&3 rep in lanes 0..3) holds mod-4 partials
        #pragma unroll
        for (int o = 16; o >= 4; o >>= 1) {
            s0 += __shfl_xor_sync(0xffffffffu, s0, o);
            s1 += __shfl_xor_sync(0xffffffffu, s1, o);
            s2 += __shfl_xor_sync(0xffffffffu, s2, o);
            s3 += __shfl_xor_sync(0xffffffffu, s3, o);
        }
        if (lane < 4) {
            part_s[group][0][chunk][lane] = s0;
            part_s[group][1][chunk][lane] = s1;
            part_s[group][2][chunk][lane] = s2;
            part_s[group][3][chunk][lane] = s3;
        }
        __syncthreads();  // C

        // Warp 0 tail: lane r = gate row (unit u=r>>2, gate j=r&3)
        if (warp == 0) {
            int u = lane >> 2, j = lane & 3;
            const float4* pp = (const float4*)&part_s[u][j][0][0];
            float4 p0 = pp[0], p1 = pp[1], p2 = pp[2], p3 = pp[3];
            float s = ((p0.x + p0.y) + (p0.z + p0.w)) + ((p1.x + p1.y) + (p1.z + p1.w))
                    + ((p2.x + p2.y) + (p2.z + p2.w)) + ((p3.x + p3.y) + (p3.z + p3.w))
                    + xg_cur;
            // activation: gate 2 -> tanh, else sigmoid (same math as before)
            float act = (j == 2) ? tanh_fast(s) : sigm(s);
            float fv = __shfl_down_sync(0xffffffffu, act, 1);
            float gv = __shfl_down_sync(0xffffffffu, act, 2);
            float ov = __shfl_down_sync(0xffffffffu, act, 3);
            if (j == 0) {
                c_reg = fmaf(fv, c_reg, act * gv);          // act = i
                float h = ov * tanh_fast(c_reg);
                g_hs[(size_t)t * HID + b * UPB + u] = h;
            }
            __syncwarp();
            if (lane == 0) red_add_release(&g_cnt, 1);      // h stores ordered before publish
            xg_cur = xg_nxt;
        }
    }
}

// ---------------- head: out[s] = sigmoid(hs(s+1) . v + bc) ----------------
__global__ void head_kernel(float* __restrict__ out) {
    int s = blockIdx.x;
    int tid = threadIdx.x;  // 128
    const float* hrow = g_hs + (size_t)(s + 1) * HID;
    float p = 0.f;
    #pragma unroll
    for (int k = 0; k < 8; k++)
        p = fmaf(hrow[tid + 128 * k], g_v[tid + 128 * k], p);
    #pragma unroll
    for (int o = 16; o; o >>= 1) p += __shfl_xor_sync(0xffffffffu, p, o);
    __shared__ float red[4];
    if ((tid & 31) == 0) red[tid >> 5] = p;
    __syncthreads();
    if (tid == 0) {
        float tot = red[0] + red[1] + red[2] + red[3] + g_bc;
        out[s] = sigm(tot);
    }
}

// ---------------- launch ----------------
extern "C" void kernel_launch(void* const* d_in, const int* in_sizes, int n_in,
                              void* d_out, int out_size) {
    const int*   sentence = (const int*)  d_in[0];
    const float* emb      = (const float*)d_in[1];
    const float* W_ih     = (const float*)d_in[2];
    const float* W_hh     = (const float*)d_in[3];
    const float* b_ih     = (const float*)d_in[4];
    const float* b_hh     = (const float*)d_in[5];
    const float* W_tag    = (const float*)d_in[6];
    const float* b_tag    = (const float*)d_in[7];
    const float* W_hyb    = (const float*)d_in[8];
    const float* b_hyb    = (const float*)d_in[9];
    float* out = (float*)d_out;

    init_kernel<<<1, 1024>>>(b_tag, W_hyb, b_hyb);
    vprec_kernel<<<1, 1024>>>(W_tag, W_hyb);
    dim3 g(G4H / BN, S_LEN / BM);
    gemm_xgates<<<g, 256>>>(sentence, emb, W_ih, b_ih, b_hh);
    lstm_rec<<<NBLK, 1024>>>(W_hh);
    head_kernel<<<S_LEN, 128>>>(out);
}

// round 7
// speedup vs baseline: 3.0758x; 1.0023x over previous
#include <cuda_runtime.h>
#include <cstdint>
#include <cstddef>

// Problem dims
#define S_LEN 4096
#define HID   1024
#define EMB   1024
#define G4H   4096   // 4*HID
#define NBLK  128    // persistent recurrence blocks (1 per SM)
#define UPB   8      // hidden units per block (128*8 = 1024)

// ---------------- scratch (static device memory; no allocation) ----------------
__device__ __align__(16) float g_xgates[(size_t)S_LEN * G4H];   // 67 MB
__device__ __align__(16) float g_hs[(size_t)(S_LEN + 1) * HID]; // h(0..S); row 0 zeros
__device__ int   g_cnt;                                          // global step-completion counter
__device__ float g_v[HID];                                       // W_tag^T @ w_hyb
__device__ float g_bc;                                           // b_tag.w_hyb + b_hyb

// ---------------- helpers (STRONG ops only for sync) ----------------
__device__ __forceinline__ int ld_acq(const int* p) {
    int v;
    asm volatile("ld.global.acquire.gpu.b32 %0, [%1];" : "=r"(v) : "l"(p) : "memory");
    return v;
}
__device__ __forceinline__ void red_add_release(int* p, int v) {
    asm volatile("red.release.gpu.global.add.s32 [%0], %1;" :: "l"(p), "r"(v) : "memory");
}
__device__ __forceinline__ void fma2(unsigned long long& d, unsigned long long a, unsigned long long b) {
    asm("fma.rn.f32x2 %0, %1, %2, %0;" : "+l"(d) : "l"(a), "l"(b));
}
__device__ __forceinline__ float2 unpack2(unsigned long long v) {
    float2 f;
    asm("mov.b64 {%0,%1}, %2;" : "=f"(f.x), "=f"(f.y) : "l"(v));
    return f;
}
__device__ __forceinline__ float sigm(float x) { return 1.f / (1.f + __expf(-x)); }
__device__ __forceinline__ float tanh_fast(float x) { return 2.f / (1.f + __expf(-2.f * x)) - 1.f; }

// ---------------- init: h0 = 0, counter = 0, head bias constant ----------------
__global__ void init_kernel(const float* __restrict__ b_tag,
                            const float* __restrict__ w_hyb,
                            const float* __restrict__ b_hyb) {
    int tid = threadIdx.x;               // 1024 threads
    if (tid < HID) g_hs[tid] = 0.f;      // h(0) = 0
    if (tid == 0) g_cnt = 0;             // step counter
    if (tid < 32) {
        float s = 0.f;
        for (int k = tid; k < HID; k += 32) s = fmaf(b_tag[k], w_hyb[k], s);
        #pragma unroll
        for (int o = 16; o; o >>= 1) s += __shfl_xor_sync(0xffffffffu, s, o);
        if (tid == 0) g_bc = s + b_hyb[0];
    }
}

// ---------------- head precompute: v[j] = sum_t w_hyb[t] * W_tag[t][j] ----------------
__global__ void vprec_kernel(const float* __restrict__ W_tag,
                             const float* __restrict__ w_hyb) {
    int j = threadIdx.x;  // 1024 threads
    float s = 0.f;
    #pragma unroll 8
    for (int t = 0; t < HID; t++)
        s = fmaf(__ldg(&w_hyb[t]), __ldg(&W_tag[(size_t)t * HID + j]), s);
    g_v[j] = s;
}

// ---------------- front GEMM: g_xgates[s][n] = emb[sentence[s]] . W_ih[n] + bias ----------------
// 128x128x8 tiles, 256 threads, 8x8 micro-tile, double-buffered smem.
#define GBM 128
#define GBN 128
#define GBK 8

__global__ void __launch_bounds__(256) gemm_xgates(
    const int*   __restrict__ sentence,
    const float* __restrict__ emb,
    const float* __restrict__ W_ih,
    const float* __restrict__ b_ih,
    const float* __restrict__ b_hh) {
    __shared__ int sids[GBM];
    __shared__ __align__(16) float As[2][GBK][GBM + 4];  // stride 132 floats = 528B (16B-aligned)
    __shared__ __align__(16) float Bs[2][GBK][GBN + 4];

    int tid = threadIdx.x;
    int bm = blockIdx.y, bn = blockIdx.x;
    int tx = tid & 15, ty = tid >> 4;     // 16x16 threads, 8x8 micro-tile
    int lrow = tid >> 1;                  // 0..127
    int lk   = (tid & 1) << 2;            // 0 or 4

    if (tid < GBM) sids[tid] = __ldg(&sentence[bm * GBM + tid]);
    __syncthreads();

    const float* aptr = emb + (size_t)sids[lrow] * EMB + lk;
    const float* bptr = W_ih + (size_t)(bn * GBN + lrow) * EMB + lk;

    // preload slab 0 -> buffer 0
    {
        float4 av = *(const float4*)aptr;
        float4 bv = *(const float4*)bptr;
        As[0][lk + 0][lrow] = av.x; As[0][lk + 1][lrow] = av.y;
        As[0][lk + 2][lrow] = av.z; As[0][lk + 3][lrow] = av.w;
        Bs[0][lk + 0][lrow] = bv.x; Bs[0][lk + 1][lrow] = bv.y;
        Bs[0][lk + 2][lrow] = bv.z; Bs[0][lk + 3][lrow] = bv.w;
    }
    __syncthreads();

    float acc[8][8] = {};
    int cur = 0;
    for (int kt = GBK; kt <= EMB; kt += GBK) {
        bool more = (kt < EMB);
        float4 av, bv;
        if (more) {
            av = *(const float4*)(aptr + kt);
            bv = *(const float4*)(bptr + kt);
        }
        #pragma unroll
        for (int kk = 0; kk < GBK; kk++) {
            float4 a0 = *(const float4*)&As[cur][kk][ty << 3];
            float4 a1 = *(const float4*)&As[cur][kk][(ty << 3) + 4];
            float4 b0 = *(const float4*)&Bs[cur][kk][tx << 3];
            float4 b1 = *(const float4*)&Bs[cur][kk][(tx << 3) + 4];
            float am[8] = {a0.x, a0.y, a0.z, a0.w, a1.x, a1.y, a1.z, a1.w};
            float bb[8] = {b0.x, b0.y, b0.z, b0.w, b1.x, b1.y, b1.z, b1.w};
            #pragma unroll
            for (int i = 0; i < 8; i++)
                #pragma unroll
                for (int j = 0; j < 8; j++)
                    acc[i][j] = fmaf(am[i], bb[j], acc[i][j]);
        }
        if (more) {
            int nxt = cur ^ 1;
            As[nxt][lk + 0][lrow] = av.x; As[nxt][lk + 1][lrow] = av.y;
            As[nxt][lk + 2][lrow] = av.z; As[nxt][lk + 3][lrow] = av.w;
            Bs[nxt][lk + 0][lrow] = bv.x; Bs[nxt][lk + 1][lrow] = bv.y;
            Bs[nxt][lk + 2][lrow] = bv.z; Bs[nxt][lk + 3][lrow] = bv.w;
            __syncthreads();
            cur = nxt;
        }
    }

    // epilogue: add bias, store 8x8 tile
    int n0 = bn * GBN + (tx << 3);
    float4 bi0 = *(const float4*)&b_ih[n0];
    float4 bi1 = *(const float4*)&b_ih[n0 + 4];
    float4 bh0 = *(const float4*)&b_hh[n0];
    float4 bh1 = *(const float4*)&b_hh[n0 + 4];
    float4 bl0, bl1;
    bl0.x = bi0.x + bh0.x; bl0.y = bi0.y + bh0.y;
    bl0.z = bi0.z + bh0.z; bl0.w = bi0.w + bh0.w;
    bl1.x = bi1.x + bh1.x; bl1.y = bi1.y + bh1.y;
    bl1.z = bi1.z + bh1.z; bl1.w = bi1.w + bh1.w;
    #pragma unroll
    for (int i = 0; i < 8; i++) {
        int m = bm * GBM + (ty << 3) + i;
        float4 o0, o1;
        o0.x = acc[i][0] + bl0.x; o0.y = acc[i][1] + bl0.y;
        o0.z = acc[i][2] + bl0.z; o0.w = acc[i][3] + bl0.w;
        o1.x = acc[i][4] + bl1.x; o1.y = acc[i][5] + bl1.y;
        o1.z = acc[i][6] + bl1.z; o1.w = acc[i][7] + bl1.w;
        float* dst = &g_xgates[(size_t)m * G4H + n0];
        *(float4*)dst = o0;
        *(float4*)(dst + 4) = o1;
    }
}

// ---------------- persistent LSTM recurrence (lean step, strong sync; R6-proven) ----------------
__global__ void __launch_bounds__(1024, 1) lstm_rec(const float* __restrict__ W_hh) {
    // part_s[g][j][c][q]: unit-group g, gate j, chunk c, lane-group q
    __shared__ float part_s[8][4][4][4];

    int tid  = threadIdx.x;
    int lane = tid & 31, warp = tid >> 5;
    int group = warp >> 2, chunk = warp & 3;
    int b = blockIdx.x;
    int unit = b * UPB + group;

    // Packed register weights: w2[j][k] covers elements (c*256 + 2*lane + 64k, +1)
    unsigned long long w2[4][4];
    #pragma unroll
    for (int j = 0; j < 4; j++) {
        const float* wr = W_hh + (size_t)(j * HID + unit) * HID + (chunk << 8) + (lane << 1);
        #pragma unroll
        for (int k = 0; k < 4; k++)
            w2[j][k] = *(const unsigned long long*)(wr + 64 * k);
    }

    float c_reg = 0.f;
    float xg_cur = 0.f;
    if (warp == 0)
        xg_cur = __ldg(&g_xgates[(size_t)0 * G4H + (lane & 3) * HID + b * UPB + (lane >> 2)]);

    __syncthreads();

    int tgt = 0;  // = NBLK * (t-1)
    for (int t = 1; t <= S_LEN; t++, tgt += NBLK) {
        // Poller: warp 1 lane 0 acquire-spins on the global counter
        if (tid == 32) {
            while (ld_acq(&g_cnt) < tgt) { }
        }
        __syncthreads();  // A: h(t-1) globally visible to the whole block

        // Warp 0: prefetch next step's xg
        float xg_nxt = 0.f;
        if (warp == 0) {
            int tp = (t < S_LEN) ? t : 0;
            xg_nxt = __ldg(&g_xgates[(size_t)tp * G4H + (lane & 3) * HID + b * UPB + (lane >> 2)]);
        }

        // Direct global loads of this thread's 4 h pairs
        const float* hrow = g_hs + (size_t)(t - 1) * HID + (chunk << 8) + (lane << 1);
        unsigned long long h0 = *(const unsigned long long*)(hrow);
        unsigned long long h1 = *(const unsigned long long*)(hrow + 64);
        unsigned long long h2 = *(const unsigned long long*)(hrow + 128);
        unsigned long long h3 = *(const unsigned long long*)(hrow + 192);

        // Packed dots: 4 gate rows x 4 pairs
        unsigned long long a2_0 = 0ull, a2_1 = 0ull, a2_2 = 0ull, a2_3 = 0ull;
        fma2(a2_0, w2[0][0], h0); fma2(a2_1, w2[1][0], h0);
        fma2(a2_2, w2[2][0], h0); fma2(a2_3, w2[3][0], h0);
        fma2(a2_0, w2[0][1], h1); fma2(a2_1, w2[1][1], h1);
        fma2(a2_2, w2[2][1], h1); fma2(a2_3, w2[3][1], h1);
        fma2(a2_0, w2[0][2], h2); fma2(a2_1, w2[1][2], h2);
        fma2(a2_2, w2[2][2], h2); fma2(a2_3, w2[3][2], h2);
        fma2(a2_0, w2[0][3], h3); fma2(a2_1, w2[1][3], h3);
        fma2(a2_2, w2[2][3], h3); fma2(a2_3, w2[3][3], h3);

        float2 f0 = unpack2(a2_0), f1 = unpack2(a2_1), f2 = unpack2(a2_2), f3 = unpack2(a2_3);
        float s0 = f0.x + f0.y, s1 = f1.x + f1.y, s2 = f2.x + f2.y, s3 = f3.x + f3.y;

        #pragma unroll
        for (int o = 16; o >= 4; o >>= 1) {
            s0 += __shfl_xor_sync(0xffffffffu, s0, o);
            s1 += __shfl_xor_sync(0xffffffffu, s1, o);
            s2 += __shfl_xor_sync(0xffffffffu, s2, o);
            s3 += __shfl_xor_sync(0xffffffffu, s3, o);
        }
        if (lane < 4) {
            part_s[group][0][chunk][lane] = s0;
            part_s[group][1][chunk][lane] = s1;
            part_s[group][2][chunk][lane] = s2;
            part_s[group][3][chunk][lane] = s3;
        }
        __syncthreads();  // C

        // Warp 0 tail: lane r = gate row (unit u=r>>2, gate j=r&3)
        if (warp == 0) {
            int u = lane >> 2, j = lane & 3;
            const float4* pp = (const float4*)&part_s[u][j][0][0];
            float4 p0 = pp[0], p1 = pp[1], p2 = pp[2], p3 = pp[3];
            float s = ((p0.x + p0.y) + (p0.z + p0.w)) + ((p1.x + p1.y) + (p1.z + p1.w))
                    + ((p2.x + p2.y) + (p2.z + p2.w)) + ((p3.x + p3.y) + (p3.z + p3.w))
                    + xg_cur;
            float act = (j == 2) ? tanh_fast(s) : sigm(s);
            float fv = __shfl_down_sync(0xffffffffu, act, 1);
            float gv = __shfl_down_sync(0xffffffffu, act, 2);
            float ov = __shfl_down_sync(0xffffffffu, act, 3);
            if (j == 0) {
                c_reg = fmaf(fv, c_reg, act * gv);          // act = i
                float h = ov * tanh_fast(c_reg);
                g_hs[(size_t)t * HID + b * UPB + u] = h;
            }
            __syncwarp();
            if (lane == 0) red_add_release(&g_cnt, 1);
            xg_cur = xg_nxt;
        }
    }
}

// ---------------- head: out[s] = sigmoid(hs(s+1) . v + bc) ----------------
__global__ void head_kernel(float* __restrict__ out) {
    int s = blockIdx.x;
    int tid = threadIdx.x;  // 128
    const float* hrow = g_hs + (size_t)(s + 1) * HID;
    float p = 0.f;
    #pragma unroll
    for (int k = 0; k < 8; k++)
        p = fmaf(hrow[tid + 128 * k], g_v[tid + 128 * k], p);
    #pragma unroll
    for (int o = 16; o; o >>= 1) p += __shfl_xor_sync(0xffffffffu, p, o);
    __shared__ float red[4];
    if ((tid & 31) == 0) red[tid >> 5] = p;
    __syncthreads();
    if (tid == 0) {
        float tot = red[0] + red[1] + red[2] + red[3] + g_bc;
        out[s] = sigm(tot);
    }
}

// ---------------- launch ----------------
extern "C" void kernel_launch(void* const* d_in, const int* in_sizes, int n_in,
                              void* d_out, int out_size) {
    const int*   sentence = (const int*)  d_in[0];
    const float* emb      = (const float*)d_in[1];
    const float* W_ih     = (const float*)d_in[2];
    const float* W_hh     = (const float*)d_in[3];
    const float* b_ih     = (const float*)d_in[4];
    const float* b_hh     = (const float*)d_in[5];
    const float* W_tag    = (const float*)d_in[6];
    const float* b_tag    = (const float*)d_in[7];
    const float* W_hyb    = (const float*)d_in[8];
    const float* b_hyb    = (const float*)d_in[9];
    float* out = (float*)d_out;

    init_kernel<<<1, 1024>>>(b_tag, W_hyb, b_hyb);
    vprec_kernel<<<1, 1024>>>(W_tag, W_hyb);
    dim3 g(G4H / GBN, S_LEN / GBM);
    gemm_xgates<<<g, 256>>>(sentence, emb, W_ih, b_ih, b_hh);
    lstm_rec<<<NBLK, 1024>>>(W_hh);
    head_kernel<<<S_LEN, 128>>>(out);
}